// round 1
// baseline (speedup 1.0000x reference)
#include <cuda_runtime.h>

#define B_  2
#define S_  2048
#define D_  512
#define H_  8
#define DH_ 64
#define MM_ 2048          // MAX_SEQ (== S here)
#define BH_ (B_*H_)

// ---------------- scratch (static __device__, no allocation) ----------------
__device__ float g_Qp[B_*S_*D_];                 // 8 MB
__device__ float g_Kp[B_*S_*D_];                 // 8 MB
__device__ float g_Vp[B_*S_*D_];                 // 8 MB
__device__ float g_tmp[B_*S_*D_];                // 8 MB  (attn @ V, head-merged)
__device__ float g_QE[(size_t)BH_*S_*MM_];       // 256 MB (Q @ E^T per b,h)

// ============================================================================
// Generic NN SGEMM + bias: C[M,N] = A[M,K] @ B[K,N] + bias[N]
// BM=BN=128, BK=16, 256 threads, 8x8 per thread.
// ============================================================================
__global__ void sgemm_nn_bias(const float* __restrict__ A,
                              const float* __restrict__ Bm,
                              const float* __restrict__ bias,
                              float* __restrict__ C,
                              int M, int N, int K)
{
    __shared__ float As[16][132];
    __shared__ float Bs[16][132];
    const int bm = blockIdx.y * 128;
    const int bn = blockIdx.x * 128;
    const int tid = threadIdx.x;
    const int tx = tid & 15, ty = tid >> 4;

    float acc[8][8];
#pragma unroll
    for (int i = 0; i < 8; i++)
#pragma unroll
        for (int j = 0; j < 8; j++) acc[i][j] = 0.f;

    for (int k0 = 0; k0 < K; k0 += 16) {
#pragma unroll
        for (int l = 0; l < 2; l++) {
            int v = tid + l * 256;
            // A tile: 128 rows x 16 k  (scatter-transpose into As[k][m])
            int row = v >> 2, kc = (v & 3) * 4;
            float4 a = *(const float4*)(A + (size_t)(bm + row) * K + k0 + kc);
            As[kc+0][row] = a.x; As[kc+1][row] = a.y;
            As[kc+2][row] = a.z; As[kc+3][row] = a.w;
            // B tile: 16 k x 128 n
            int kr = v >> 5, nc = (v & 31) * 4;
            float4 b = *(const float4*)(Bm + (size_t)(k0 + kr) * N + bn + nc);
            Bs[kr][nc+0] = b.x; Bs[kr][nc+1] = b.y;
            Bs[kr][nc+2] = b.z; Bs[kr][nc+3] = b.w;
        }
        __syncthreads();
#pragma unroll
        for (int kk = 0; kk < 16; kk++) {
            float4 a0 = *(const float4*)&As[kk][ty*8];
            float4 a1 = *(const float4*)&As[kk][ty*8+4];
            float4 b0 = *(const float4*)&Bs[kk][tx*8];
            float4 b1 = *(const float4*)&Bs[kk][tx*8+4];
            float ar[8] = {a0.x,a0.y,a0.z,a0.w,a1.x,a1.y,a1.z,a1.w};
            float br[8] = {b0.x,b0.y,b0.z,b0.w,b1.x,b1.y,b1.z,b1.w};
#pragma unroll
            for (int i = 0; i < 8; i++)
#pragma unroll
                for (int j = 0; j < 8; j++) acc[i][j] += ar[i]*br[j];
        }
        __syncthreads();
    }
#pragma unroll
    for (int i = 0; i < 8; i++) {
        int r = bm + ty*8 + i;
#pragma unroll
        for (int j = 0; j < 8; j += 4) {
            int c = bn + tx*8 + j;
            float4 o = make_float4(acc[i][j+0] + bias[c+0],
                                   acc[i][j+1] + bias[c+1],
                                   acc[i][j+2] + bias[c+2],
                                   acc[i][j+3] + bias[c+3]);
            *(float4*)(C + (size_t)r * N + c) = o;
        }
    }
}

// ============================================================================
// QE GEMM (NT): QE[bh][i][r] = sum_d Qp[b,i,h*64+d] * E[r,d]   (K = 64)
// ============================================================================
__global__ void gemm_qe(const float* __restrict__ Qp,
                        const float* __restrict__ E,
                        float* __restrict__ QE)
{
    const int bh = blockIdx.z;
    const float* A = Qp + (size_t)(bh >> 3) * S_ * D_ + (bh & 7) * DH_;
    const int bm = blockIdx.y * 128;   // i
    const int bn = blockIdx.x * 128;   // r
    const int tid = threadIdx.x;
    const int tx = tid & 15, ty = tid >> 4;

    __shared__ float As[16][132];
    __shared__ float Bs[16][132];
    float acc[8][8];
#pragma unroll
    for (int i = 0; i < 8; i++)
#pragma unroll
        for (int j = 0; j < 8; j++) acc[i][j] = 0.f;

    for (int k0 = 0; k0 < DH_; k0 += 16) {
#pragma unroll
        for (int l = 0; l < 2; l++) {
            int v = tid + l * 256;
            int row = v >> 2, kc = (v & 3) * 4;
            float4 a = *(const float4*)(A + (size_t)(bm + row) * D_ + k0 + kc);
            As[kc+0][row] = a.x; As[kc+1][row] = a.y;
            As[kc+2][row] = a.z; As[kc+3][row] = a.w;
            float4 b = *(const float4*)(E + (size_t)(bn + row) * DH_ + k0 + kc);
            Bs[kc+0][row] = b.x; Bs[kc+1][row] = b.y;
            Bs[kc+2][row] = b.z; Bs[kc+3][row] = b.w;
        }
        __syncthreads();
#pragma unroll
        for (int kk = 0; kk < 16; kk++) {
            float4 a0 = *(const float4*)&As[kk][ty*8];
            float4 a1 = *(const float4*)&As[kk][ty*8+4];
            float4 b0 = *(const float4*)&Bs[kk][tx*8];
            float4 b1 = *(const float4*)&Bs[kk][tx*8+4];
            float ar[8] = {a0.x,a0.y,a0.z,a0.w,a1.x,a1.y,a1.z,a1.w};
            float br[8] = {b0.x,b0.y,b0.z,b0.w,b1.x,b1.y,b1.z,b1.w};
#pragma unroll
            for (int i = 0; i < 8; i++)
#pragma unroll
                for (int j = 0; j < 8; j++) acc[i][j] += ar[i]*br[j];
        }
        __syncthreads();
    }
    float* Cb = QE + (size_t)bh * S_ * MM_;
#pragma unroll
    for (int i = 0; i < 8; i++) {
        int r = bm + ty*8 + i;
#pragma unroll
        for (int j = 0; j < 8; j += 4) {
            float4 o = make_float4(acc[i][j], acc[i][j+1], acc[i][j+2], acc[i][j+3]);
            *(float4*)(Cb + (size_t)r * MM_ + bn + tx*8 + j) = o;
        }
    }
}

// ============================================================================
// Logits (NT, causal): attn[bh][i][j] = (Q_h[i]·K_h[j] + QE[bh][i][j-i+M-1]) / 8
// only stored for j <= i.
// ============================================================================
__global__ void logits_kernel(const float* __restrict__ Qp,
                              const float* __restrict__ Kp,
                              const float* __restrict__ QE,
                              float* __restrict__ attn)
{
    const int bm = blockIdx.y * 128;   // i
    const int bn = blockIdx.x * 128;   // j
    if (bn > bm + 127) return;         // fully masked tile
    const int bh = blockIdx.z;
    const float* A  = Qp + (size_t)(bh >> 3) * S_ * D_ + (bh & 7) * DH_;
    const float* Bt = Kp + (size_t)(bh >> 3) * S_ * D_ + (bh & 7) * DH_;
    const int tid = threadIdx.x;
    const int tx = tid & 15, ty = tid >> 4;

    __shared__ float As[16][132];
    __shared__ float Bs[16][132];
    float acc[8][8];
#pragma unroll
    for (int i = 0; i < 8; i++)
#pragma unroll
        for (int j = 0; j < 8; j++) acc[i][j] = 0.f;

    for (int k0 = 0; k0 < DH_; k0 += 16) {
#pragma unroll
        for (int l = 0; l < 2; l++) {
            int v = tid + l * 256;
            int row = v >> 2, kc = (v & 3) * 4;
            float4 a = *(const float4*)(A  + (size_t)(bm + row) * D_ + k0 + kc);
            As[kc+0][row] = a.x; As[kc+1][row] = a.y;
            As[kc+2][row] = a.z; As[kc+3][row] = a.w;
            float4 b = *(const float4*)(Bt + (size_t)(bn + row) * D_ + k0 + kc);
            Bs[kc+0][row] = b.x; Bs[kc+1][row] = b.y;
            Bs[kc+2][row] = b.z; Bs[kc+3][row] = b.w;
        }
        __syncthreads();
#pragma unroll
        for (int kk = 0; kk < 16; kk++) {
            float4 a0 = *(const float4*)&As[kk][ty*8];
            float4 a1 = *(const float4*)&As[kk][ty*8+4];
            float4 b0 = *(const float4*)&Bs[kk][tx*8];
            float4 b1 = *(const float4*)&Bs[kk][tx*8+4];
            float ar[8] = {a0.x,a0.y,a0.z,a0.w,a1.x,a1.y,a1.z,a1.w};
            float br[8] = {b0.x,b0.y,b0.z,b0.w,b1.x,b1.y,b1.z,b1.w};
#pragma unroll
            for (int i = 0; i < 8; i++)
#pragma unroll
                for (int j = 0; j < 8; j++) acc[i][j] += ar[i]*br[j];
        }
        __syncthreads();
    }
    const float* QEr = QE + (size_t)bh * S_ * MM_;
    float* Cb = attn + (size_t)bh * S_ * S_;
#pragma unroll
    for (int i2 = 0; i2 < 8; i2++) {
        int i = bm + ty*8 + i2;
#pragma unroll
        for (int j2 = 0; j2 < 8; j2++) {
            int j = bn + tx*8 + j2;
            if (j <= i) {
                float srel = QEr[(size_t)i * MM_ + (j - i + MM_ - 1)];
                Cb[(size_t)i * S_ + j] = (acc[i2][j2] + srel) * 0.125f;
            }
        }
    }
}

// ============================================================================
// Causal row softmax, in place.  One block per (b,h,i) row.
// Also zero-fills the masked tail (j > i) — reference gives exact 0 there.
// ============================================================================
__global__ void softmax_causal(float* __restrict__ attn)
{
    const int row = blockIdx.x;          // bh*S + i
    const int i   = row & (S_ - 1);
    float* p = attn + (size_t)row * S_;
    const int len = i + 1;
    const int tid = threadIdx.x;
    __shared__ float red[256];

    float mx = -1e30f;
    for (int j = tid; j < len; j += 256) mx = fmaxf(mx, p[j]);
    red[tid] = mx; __syncthreads();
    for (int s = 128; s > 0; s >>= 1) {
        if (tid < s) red[tid] = fmaxf(red[tid], red[tid + s]);
        __syncthreads();
    }
    mx = red[0]; __syncthreads();

    float sum = 0.f;
    for (int j = tid; j < len; j += 256) sum += __expf(p[j] - mx);
    red[tid] = sum; __syncthreads();
    for (int s = 128; s > 0; s >>= 1) {
        if (tid < s) red[tid] += red[tid + s];
        __syncthreads();
    }
    const float inv = 1.f / red[0];

    for (int j = tid; j < len; j += 256) p[j] = __expf(p[j] - mx) * inv;
    for (int j = len + tid; j < S_; j += 256) p[j] = 0.f;
}

// ============================================================================
// AV GEMM (causal):  tmp[b, i, h*64+d] = sum_{j<=i} attn[bh][i][j] * Vp[b,j,h*64+d]
// BM=128 (i), BN=64 (d), BK=16; attn rows beyond i are exact zeros.
// ============================================================================
__global__ void av_kernel(const float* __restrict__ attn,
                          const float* __restrict__ Vp,
                          float* __restrict__ Ot)
{
    const int bh = blockIdx.z;
    const int b = bh >> 3, h = bh & 7;
    const int bm = blockIdx.y * 128;
    const float* Ar = attn + (size_t)bh * S_ * S_;
    const float* Vr = Vp + (size_t)b * S_ * D_ + h * DH_;
    const int tid = threadIdx.x;
    const int tx = tid & 15, ty = tid >> 4;

    __shared__ float As[16][132];
    __shared__ float Bs[16][68];
    float acc[8][4];
#pragma unroll
    for (int i = 0; i < 8; i++)
#pragma unroll
        for (int j = 0; j < 4; j++) acc[i][j] = 0.f;

    const int kend = bm + 128;   // strictly-upper tiles contribute zero
    for (int k0 = 0; k0 < kend; k0 += 16) {
#pragma unroll
        for (int l = 0; l < 2; l++) {
            int v = tid + l * 256;
            int row = v >> 2, kc = (v & 3) * 4;
            float4 a = *(const float4*)(Ar + (size_t)(bm + row) * S_ + k0 + kc);
            As[kc+0][row] = a.x; As[kc+1][row] = a.y;
            As[kc+2][row] = a.z; As[kc+3][row] = a.w;
        }
        {
            int kr = tid >> 4, nc = (tid & 15) * 4;
            float4 bv = *(const float4*)(Vr + (size_t)(k0 + kr) * D_ + nc);
            Bs[kr][nc+0] = bv.x; Bs[kr][nc+1] = bv.y;
            Bs[kr][nc+2] = bv.z; Bs[kr][nc+3] = bv.w;
        }
        __syncthreads();
#pragma unroll
        for (int kk = 0; kk < 16; kk++) {
            float4 a0 = *(const float4*)&As[kk][ty*8];
            float4 a1 = *(const float4*)&As[kk][ty*8+4];
            float4 b0 = *(const float4*)&Bs[kk][tx*4];
            float ar[8] = {a0.x,a0.y,a0.z,a0.w,a1.x,a1.y,a1.z,a1.w};
            float br[4] = {b0.x,b0.y,b0.z,b0.w};
#pragma unroll
            for (int i = 0; i < 8; i++)
#pragma unroll
                for (int j = 0; j < 4; j++) acc[i][j] += ar[i]*br[j];
        }
        __syncthreads();
    }
    float* Ob = Ot + (size_t)b * S_ * D_ + h * DH_;
#pragma unroll
    for (int i = 0; i < 8; i++) {
        int r = bm + ty*8 + i;
        float4 o = make_float4(acc[i][0], acc[i][1], acc[i][2], acc[i][3]);
        *(float4*)(Ob + (size_t)r * D_ + tx*4) = o;
    }
}

// ============================================================================
// launch
// ============================================================================
extern "C" void kernel_launch(void* const* d_in, const int* in_sizes, int n_in,
                              void* d_out, int out_size)
{
    const float* v  = (const float*)d_in[0];
    const float* k  = (const float*)d_in[1];
    const float* q  = (const float*)d_in[2];
    // d_in[3] = mask (implemented analytically)
    const float* Wq = (const float*)d_in[4];
    const float* bq = (const float*)d_in[5];
    const float* Wk = (const float*)d_in[6];
    const float* bk = (const float*)d_in[7];
    const float* Wv = (const float*)d_in[8];
    const float* bv = (const float*)d_in[9];
    const float* Wo = (const float*)d_in[10];
    const float* bo = (const float*)d_in[11];
    const float* E  = (const float*)d_in[12];

    float* out  = (float*)d_out;                       // (B,S,D)
    float* attn = (float*)d_out + (size_t)B_*S_*D_;    // (B,H,S,S)

    float *Qp, *Kp, *Vp, *Tmp, *QE;
    cudaGetSymbolAddress((void**)&Qp,  g_Qp);
    cudaGetSymbolAddress((void**)&Kp,  g_Kp);
    cudaGetSymbolAddress((void**)&Vp,  g_Vp);
    cudaGetSymbolAddress((void**)&Tmp, g_tmp);
    cudaGetSymbolAddress((void**)&QE,  g_QE);

    const int MROWS = B_ * S_;              // 4096
    dim3 gProj(D_ / 128, MROWS / 128);      // (4, 32)

    sgemm_nn_bias<<<gProj, 256>>>(q, Wq, bq, Qp, MROWS, D_, D_);
    sgemm_nn_bias<<<gProj, 256>>>(k, Wk, bk, Kp, MROWS, D_, D_);
    sgemm_nn_bias<<<gProj, 256>>>(v, Wv, bv, Vp, MROWS, D_, D_);

    dim3 gQE(MM_ / 128, S_ / 128, BH_);     // (16, 16, 16)
    gemm_qe<<<gQE, 256>>>(Qp, E, QE);

    dim3 gLg(S_ / 128, S_ / 128, BH_);      // (16, 16, 16), upper tiles early-exit
    logits_kernel<<<gLg, 256>>>(Qp, Kp, QE, attn);

    softmax_causal<<<BH_ * S_, 256>>>(attn);

    dim3 gAV(1, S_ / 128, BH_);             // (1, 16, 16)
    av_kernel<<<gAV, 256>>>(attn, Vp, Tmp);

    sgemm_nn_bias<<<gProj, 256>>>(Tmp, Wo, bo, out, MROWS, D_, D_);
}

// round 3
// speedup vs baseline: 1.4040x; 1.4040x over previous
#include <cuda_runtime.h>

#define B_  2
#define S_  2048
#define D_  512
#define H_  8
#define DH_ 64
#define MM_ 2048          // MAX_SEQ (== S here)
#define BH_ (B_*H_)

// ---------------- scratch (static __device__, no allocation) ----------------
__device__ float g_Qp[B_*S_*D_];                 // 8 MB
__device__ float g_Kp[B_*S_*D_];                 // 8 MB
__device__ float g_Vp[B_*S_*D_];                 // 8 MB
__device__ float g_tmp[B_*S_*D_];                // 8 MB  (AV partial, k-half 0)
__device__ float g_tmp2[B_*S_*D_];               // 8 MB  (AV partial, k-half 1)
__device__ float g_QE[(size_t)BH_*S_*MM_];       // 256 MB (Q @ E^T per b,h)

// ============================================================================
// Fused QKV projection: z=0/1/2 -> Q/K/V.  C[4096,512] = A @ W + b.
// BM=BN=128, BK=16, 256 threads, 8x8 per thread.
// ============================================================================
__global__ void proj_qkv(const float* __restrict__ q,  const float* __restrict__ k,
                         const float* __restrict__ v,
                         const float* __restrict__ Wq, const float* __restrict__ bq,
                         const float* __restrict__ Wk, const float* __restrict__ bk,
                         const float* __restrict__ Wv, const float* __restrict__ bv,
                         float* __restrict__ Qp, float* __restrict__ Kp,
                         float* __restrict__ Vp)
{
    const float *A, *W, *bias; float* C;
    if (blockIdx.z == 0)      { A = q; W = Wq; bias = bq; C = Qp; }
    else if (blockIdx.z == 1) { A = k; W = Wk; bias = bk; C = Kp; }
    else                      { A = v; W = Wv; bias = bv; C = Vp; }

    __shared__ float As[16][132];
    __shared__ float Bs[16][132];
    const int bm = blockIdx.y * 128;
    const int bn = blockIdx.x * 128;
    const int tid = threadIdx.x;
    const int tx = tid & 15, ty = tid >> 4;

    float acc[8][8];
#pragma unroll
    for (int i = 0; i < 8; i++)
#pragma unroll
        for (int j = 0; j < 8; j++) acc[i][j] = 0.f;

    for (int k0 = 0; k0 < D_; k0 += 16) {
#pragma unroll
        for (int l = 0; l < 2; l++) {
            int vv = tid + l * 256;
            int row = vv >> 2, kc = (vv & 3) * 4;
            float4 a = *(const float4*)(A + (size_t)(bm + row) * D_ + k0 + kc);
            As[kc+0][row] = a.x; As[kc+1][row] = a.y;
            As[kc+2][row] = a.z; As[kc+3][row] = a.w;
            int kr = vv >> 5, nc = (vv & 31) * 4;
            float4 b = *(const float4*)(W + (size_t)(k0 + kr) * D_ + bn + nc);
            Bs[kr][nc+0] = b.x; Bs[kr][nc+1] = b.y;
            Bs[kr][nc+2] = b.z; Bs[kr][nc+3] = b.w;
        }
        __syncthreads();
#pragma unroll
        for (int kk = 0; kk < 16; kk++) {
            float4 a0 = *(const float4*)&As[kk][ty*8];
            float4 a1 = *(const float4*)&As[kk][ty*8+4];
            float4 b0 = *(const float4*)&Bs[kk][tx*8];
            float4 b1 = *(const float4*)&Bs[kk][tx*8+4];
            float ar[8] = {a0.x,a0.y,a0.z,a0.w,a1.x,a1.y,a1.z,a1.w};
            float br[8] = {b0.x,b0.y,b0.z,b0.w,b1.x,b1.y,b1.z,b1.w};
#pragma unroll
            for (int i = 0; i < 8; i++)
#pragma unroll
                for (int j = 0; j < 8; j++) acc[i][j] += ar[i]*br[j];
        }
        __syncthreads();
    }
#pragma unroll
    for (int i = 0; i < 8; i++) {
        int r = bm + ty*8 + i;
#pragma unroll
        for (int j = 0; j < 8; j += 4) {
            int c = bn + tx*8 + j;
            float4 o = make_float4(acc[i][j+0] + bias[c+0],
                                   acc[i][j+1] + bias[c+1],
                                   acc[i][j+2] + bias[c+2],
                                   acc[i][j+3] + bias[c+3]);
            *(float4*)(C + (size_t)r * D_ + c) = o;
        }
    }
}

// ============================================================================
// Out projection with summed A: C = (A1+A2) @ W + b, M=4096, N=K=512.
// ============================================================================
__global__ void sgemm_sum2_nn_bias(const float* __restrict__ A1,
                                   const float* __restrict__ A2,
                                   const float* __restrict__ W,
                                   const float* __restrict__ bias,
                                   float* __restrict__ C)
{
    __shared__ float As[16][132];
    __shared__ float Bs[16][132];
    const int bm = blockIdx.y * 128;
    const int bn = blockIdx.x * 128;
    const int tid = threadIdx.x;
    const int tx = tid & 15, ty = tid >> 4;

    float acc[8][8];
#pragma unroll
    for (int i = 0; i < 8; i++)
#pragma unroll
        for (int j = 0; j < 8; j++) acc[i][j] = 0.f;

    for (int k0 = 0; k0 < D_; k0 += 16) {
#pragma unroll
        for (int l = 0; l < 2; l++) {
            int vv = tid + l * 256;
            int row = vv >> 2, kc = (vv & 3) * 4;
            size_t off = (size_t)(bm + row) * D_ + k0 + kc;
            float4 a  = *(const float4*)(A1 + off);
            float4 a2 = *(const float4*)(A2 + off);
            As[kc+0][row] = a.x + a2.x; As[kc+1][row] = a.y + a2.y;
            As[kc+2][row] = a.z + a2.z; As[kc+3][row] = a.w + a2.w;
            int kr = vv >> 5, nc = (vv & 31) * 4;
            float4 b = *(const float4*)(W + (size_t)(k0 + kr) * D_ + bn + nc);
            Bs[kr][nc+0] = b.x; Bs[kr][nc+1] = b.y;
            Bs[kr][nc+2] = b.z; Bs[kr][nc+3] = b.w;
        }
        __syncthreads();
#pragma unroll
        for (int kk = 0; kk < 16; kk++) {
            float4 a0 = *(const float4*)&As[kk][ty*8];
            float4 a1 = *(const float4*)&As[kk][ty*8+4];
            float4 b0 = *(const float4*)&Bs[kk][tx*8];
            float4 b1 = *(const float4*)&Bs[kk][tx*8+4];
            float ar[8] = {a0.x,a0.y,a0.z,a0.w,a1.x,a1.y,a1.z,a1.w};
            float br[8] = {b0.x,b0.y,b0.z,b0.w,b1.x,b1.y,b1.z,b1.w};
#pragma unroll
            for (int i = 0; i < 8; i++)
#pragma unroll
                for (int j = 0; j < 8; j++) acc[i][j] += ar[i]*br[j];
        }
        __syncthreads();
    }
#pragma unroll
    for (int i = 0; i < 8; i++) {
        int r = bm + ty*8 + i;
#pragma unroll
        for (int j = 0; j < 8; j += 4) {
            int c = bn + tx*8 + j;
            float4 o = make_float4(acc[i][j+0] + bias[c+0],
                                   acc[i][j+1] + bias[c+1],
                                   acc[i][j+2] + bias[c+2],
                                   acc[i][j+3] + bias[c+3]);
            *(float4*)(C + (size_t)r * D_ + c) = o;
        }
    }
}

// ============================================================================
// QE GEMM (NT), triangular: QE[bh][i][r] = sum_d Qp[b,i,h*64+d] * E[r,d]
// Only tiles with ti+tj >= 15 are ever read by logits; skip the rest.
// ============================================================================
__global__ void gemm_qe(const float* __restrict__ Qp,
                        const float* __restrict__ E,
                        float* __restrict__ QE)
{
    if (blockIdx.x + blockIdx.y < 15) return;   // never-read tiles
    const int bh = blockIdx.z;
    const float* A = Qp + (size_t)(bh >> 3) * S_ * D_ + (bh & 7) * DH_;
    const int bm = blockIdx.y * 128;   // i
    const int bn = blockIdx.x * 128;   // r
    const int tid = threadIdx.x;
    const int tx = tid & 15, ty = tid >> 4;

    __shared__ float As[16][132];
    __shared__ float Bs[16][132];
    float acc[8][8];
#pragma unroll
    for (int i = 0; i < 8; i++)
#pragma unroll
        for (int j = 0; j < 8; j++) acc[i][j] = 0.f;

    for (int k0 = 0; k0 < DH_; k0 += 16) {
#pragma unroll
        for (int l = 0; l < 2; l++) {
            int v = tid + l * 256;
            int row = v >> 2, kc = (v & 3) * 4;
            float4 a = *(const float4*)(A + (size_t)(bm + row) * D_ + k0 + kc);
            As[kc+0][row] = a.x; As[kc+1][row] = a.y;
            As[kc+2][row] = a.z; As[kc+3][row] = a.w;
            float4 b = *(const float4*)(E + (size_t)(bn + row) * DH_ + k0 + kc);
            Bs[kc+0][row] = b.x; Bs[kc+1][row] = b.y;
            Bs[kc+2][row] = b.z; Bs[kc+3][row] = b.w;
        }
        __syncthreads();
#pragma unroll
        for (int kk = 0; kk < 16; kk++) {
            float4 a0 = *(const float4*)&As[kk][ty*8];
            float4 a1 = *(const float4*)&As[kk][ty*8+4];
            float4 b0 = *(const float4*)&Bs[kk][tx*8];
            float4 b1 = *(const float4*)&Bs[kk][tx*8+4];
            float ar[8] = {a0.x,a0.y,a0.z,a0.w,a1.x,a1.y,a1.z,a1.w};
            float br[8] = {b0.x,b0.y,b0.z,b0.w,b1.x,b1.y,b1.z,b1.w};
#pragma unroll
            for (int i = 0; i < 8; i++)
#pragma unroll
                for (int j = 0; j < 8; j++) acc[i][j] += ar[i]*br[j];
        }
        __syncthreads();
    }
    float* Cb = QE + (size_t)bh * S_ * MM_;
#pragma unroll
    for (int i = 0; i < 8; i++) {
        int r = bm + ty*8 + i;
#pragma unroll
        for (int j = 0; j < 8; j += 4) {
            float4 o = make_float4(acc[i][j], acc[i][j+1], acc[i][j+2], acc[i][j+3]);
            *(float4*)(Cb + (size_t)r * MM_ + bn + tx*8 + j) = o;
        }
    }
}

// ============================================================================
// Logits (NT, causal): attn[bh][i][j] = (Q_h[i]·K_h[j] + QE[bh][i][j-i+M-1]) / 8
// only stored for j <= i.
// ============================================================================
__global__ void logits_kernel(const float* __restrict__ Qp,
                              const float* __restrict__ Kp,
                              const float* __restrict__ QE,
                              float* __restrict__ attn)
{
    const int bm = blockIdx.y * 128;   // i
    const int bn = blockIdx.x * 128;   // j
    if (bn > bm + 127) return;         // fully masked tile
    const int bh = blockIdx.z;
    const float* A  = Qp + (size_t)(bh >> 3) * S_ * D_ + (bh & 7) * DH_;
    const float* Bt = Kp + (size_t)(bh >> 3) * S_ * D_ + (bh & 7) * DH_;
    const int tid = threadIdx.x;
    const int tx = tid & 15, ty = tid >> 4;

    __shared__ float As[16][132];
    __shared__ float Bs[16][132];
    float acc[8][8];
#pragma unroll
    for (int i = 0; i < 8; i++)
#pragma unroll
        for (int j = 0; j < 8; j++) acc[i][j] = 0.f;

    for (int k0 = 0; k0 < DH_; k0 += 16) {
#pragma unroll
        for (int l = 0; l < 2; l++) {
            int v = tid + l * 256;
            int row = v >> 2, kc = (v & 3) * 4;
            float4 a = *(const float4*)(A  + (size_t)(bm + row) * D_ + k0 + kc);
            As[kc+0][row] = a.x; As[kc+1][row] = a.y;
            As[kc+2][row] = a.z; As[kc+3][row] = a.w;
            float4 b = *(const float4*)(Bt + (size_t)(bn + row) * D_ + k0 + kc);
            Bs[kc+0][row] = b.x; Bs[kc+1][row] = b.y;
            Bs[kc+2][row] = b.z; Bs[kc+3][row] = b.w;
        }
        __syncthreads();
#pragma unroll
        for (int kk = 0; kk < 16; kk++) {
            float4 a0 = *(const float4*)&As[kk][ty*8];
            float4 a1 = *(const float4*)&As[kk][ty*8+4];
            float4 b0 = *(const float4*)&Bs[kk][tx*8];
            float4 b1 = *(const float4*)&Bs[kk][tx*8+4];
            float ar[8] = {a0.x,a0.y,a0.z,a0.w,a1.x,a1.y,a1.z,a1.w};
            float br[8] = {b0.x,b0.y,b0.z,b0.w,b1.x,b1.y,b1.z,b1.w};
#pragma unroll
            for (int i = 0; i < 8; i++)
#pragma unroll
                for (int j = 0; j < 8; j++) acc[i][j] += ar[i]*br[j];
        }
        __syncthreads();
    }
    const float* QEr = QE + (size_t)bh * S_ * MM_;
    float* Cb = attn + (size_t)bh * S_ * S_;
#pragma unroll
    for (int i2 = 0; i2 < 8; i2++) {
        int i = bm + ty*8 + i2;
#pragma unroll
        for (int j2 = 0; j2 < 8; j2++) {
            int j = bn + tx*8 + j2;
            if (j <= i) {
                float srel = QEr[(size_t)i * MM_ + (j - i + MM_ - 1)];
                Cb[(size_t)i * S_ + j] = (acc[i2][j2] + srel) * 0.125f;
            }
        }
    }
}

// ============================================================================
// Causal row softmax, in place, single pass: row cached in registers,
// one global read + one expf + one store per element.
// Zero-fills the masked tail (reference gives exact 0 there).
// ============================================================================
__global__ void softmax_causal(float* __restrict__ attn)
{
    const int row = blockIdx.x;          // bh*S + i
    const int i   = row & (S_ - 1);
    float* p = attn + (size_t)row * S_;
    const int tid = threadIdx.x;

    float r[8];
    float mx = -1e30f;
#pragma unroll
    for (int l = 0; l < 8; l++) {
        int j = tid + (l << 8);
        r[l] = (j <= i) ? p[j] : -1e30f;
        mx = fmaxf(mx, r[l]);
    }
#pragma unroll
    for (int o = 16; o > 0; o >>= 1)
        mx = fmaxf(mx, __shfl_xor_sync(0xffffffffu, mx, o));
    __shared__ float smx[8];
    __shared__ float ssum[8];
    if ((tid & 31) == 0) smx[tid >> 5] = mx;
    __syncthreads();
#pragma unroll
    for (int w = 0; w < 8; w++) mx = fmaxf(mx, smx[w]);

    float sum = 0.f;
#pragma unroll
    for (int l = 0; l < 8; l++) {
        int j = tid + (l << 8);
        r[l] = (j <= i) ? __expf(r[l] - mx) : 0.f;
        sum += r[l];
    }
#pragma unroll
    for (int o = 16; o > 0; o >>= 1)
        sum += __shfl_xor_sync(0xffffffffu, sum, o);
    if ((tid & 31) == 0) ssum[tid >> 5] = sum;
    __syncthreads();
    float tot = 0.f;
#pragma unroll
    for (int w = 0; w < 8; w++) tot += ssum[w];
    const float inv = 1.f / tot;

#pragma unroll
    for (int l = 0; l < 8; l++) p[tid + (l << 8)] = r[l] * inv;
}

// ============================================================================
// AV GEMM (causal, split-K x2, heavy tiles first):
//   O{c}[b, i, h*64+d] = sum_{j in half c} attn[bh][i][j] * Vp[b,j,h*64+d]
// ============================================================================
__global__ void av_kernel(const float* __restrict__ attn,
                          const float* __restrict__ Vp,
                          float* __restrict__ O0,
                          float* __restrict__ O1)
{
    const int bh = blockIdx.z;
    const int b = bh >> 3, h = bh & 7;
    const int bm = (15 - blockIdx.y) * 128;   // heavy (large kend) tiles first
    const int kend = bm + 128;
    const int half = kend >> 1;               // multiple of 64
    const int kbeg = blockIdx.x * half;
    const int kfin = kbeg + half;
    float* Ot = blockIdx.x ? O1 : O0;

    const float* Ar = attn + (size_t)bh * S_ * S_;
    const float* Vr = Vp + (size_t)b * S_ * D_ + h * DH_;
    const int tid = threadIdx.x;
    const int tx = tid & 15, ty = tid >> 4;

    __shared__ float As[16][132];
    __shared__ float Bs[16][68];
    float acc[8][4];
#pragma unroll
    for (int i = 0; i < 8; i++)
#pragma unroll
        for (int j = 0; j < 4; j++) acc[i][j] = 0.f;

    for (int k0 = kbeg; k0 < kfin; k0 += 16) {
#pragma unroll
        for (int l = 0; l < 2; l++) {
            int v = tid + l * 256;
            int row = v >> 2, kc = (v & 3) * 4;
            float4 a = *(const float4*)(Ar + (size_t)(bm + row) * S_ + k0 + kc);
            As[kc+0][row] = a.x; As[kc+1][row] = a.y;
            As[kc+2][row] = a.z; As[kc+3][row] = a.w;
        }
        {
            int kr = tid >> 4, nc = (tid & 15) * 4;
            float4 bv = *(const float4*)(Vr + (size_t)(k0 + kr) * D_ + nc);
            Bs[kr][nc+0] = bv.x; Bs[kr][nc+1] = bv.y;
            Bs[kr][nc+2] = bv.z; Bs[kr][nc+3] = bv.w;
        }
        __syncthreads();
#pragma unroll
        for (int kk = 0; kk < 16; kk++) {
            float4 a0 = *(const float4*)&As[kk][ty*8];
            float4 a1 = *(const float4*)&As[kk][ty*8+4];
            float4 b0 = *(const float4*)&Bs[kk][tx*4];
            float ar[8] = {a0.x,a0.y,a0.z,a0.w,a1.x,a1.y,a1.z,a1.w};
            float br[4] = {b0.x,b0.y,b0.z,b0.w};
#pragma unroll
            for (int i = 0; i < 8; i++)
#pragma unroll
                for (int j = 0; j < 4; j++) acc[i][j] += ar[i]*br[j];
        }
        __syncthreads();
    }
    float* Ob = Ot + (size_t)b * S_ * D_ + h * DH_;
#pragma unroll
    for (int i = 0; i < 8; i++) {
        int r = bm + ty*8 + i;
        float4 o = make_float4(acc[i][0], acc[i][1], acc[i][2], acc[i][3]);
        *(float4*)(Ob + (size_t)r * D_ + tx*4) = o;
    }
}

// ============================================================================
// launch
// ============================================================================
extern "C" void kernel_launch(void* const* d_in, const int* in_sizes, int n_in,
                              void* d_out, int out_size)
{
    const float* v  = (const float*)d_in[0];
    const float* k  = (const float*)d_in[1];
    const float* q  = (const float*)d_in[2];
    // d_in[3] = mask (implemented analytically)
    const float* Wq = (const float*)d_in[4];
    const float* bq = (const float*)d_in[5];
    const float* Wk = (const float*)d_in[6];
    const float* bk = (const float*)d_in[7];
    const float* Wv = (const float*)d_in[8];
    const float* bv = (const float*)d_in[9];
    const float* Wo = (const float*)d_in[10];
    const float* bo = (const float*)d_in[11];
    const float* E  = (const float*)d_in[12];

    float* out  = (float*)d_out;                       // (B,S,D)
    float* attn = (float*)d_out + (size_t)B_*S_*D_;    // (B,H,S,S)

    float *Qp, *Kp, *Vp, *Tmp, *Tmp2, *QE;
    cudaGetSymbolAddress((void**)&Qp,   g_Qp);
    cudaGetSymbolAddress((void**)&Kp,   g_Kp);
    cudaGetSymbolAddress((void**)&Vp,   g_Vp);
    cudaGetSymbolAddress((void**)&Tmp,  g_tmp);
    cudaGetSymbolAddress((void**)&Tmp2, g_tmp2);
    cudaGetSymbolAddress((void**)&QE,   g_QE);

    dim3 gProj(D_ / 128, (B_*S_) / 128, 3);  // (4, 32, 3) = 384 blocks
    proj_qkv<<<gProj, 256>>>(q, k, v, Wq, bq, Wk, bk, Wv, bv, Qp, Kp, Vp);

    dim3 gQE(MM_ / 128, S_ / 128, BH_);      // (16, 16, 16), triangular early-exit
    gemm_qe<<<gQE, 256>>>(Qp, E, QE);

    dim3 gLg(S_ / 128, S_ / 128, BH_);       // (16, 16, 16), upper tiles early-exit
    logits_kernel<<<gLg, 256>>>(Qp, Kp, QE, attn);

    softmax_causal<<<BH_ * S_, 256>>>(attn);

    dim3 gAV(2, S_ / 128, BH_);              // (2, 16, 16) = 512 blocks, split-K
    av_kernel<<<gAV, 256>>>(attn, Vp, Tmp, Tmp2);

    dim3 gOut(D_ / 128, (B_*S_) / 128);      // (4, 32)
    sgemm_sum2_nn_bias<<<gOut, 256>>>(Tmp, Tmp2, Wo, bo, out);
}